// round 16
// baseline (speedup 1.0000x reference)
#include <cuda_runtime.h>
#include <cuda_bf16.h>
#include <cstdint>

// ---------------------------------------------------------------------------
// EfmLSTM round 16: GEMM/conv = round 15. Scan: 8-way k-split with
// DUPLICATED-h storage — update threads write (h,h) pairs; GEMV readers
// LDS.128 straight into FFMA2 operands (no pack MOVs). 8 LDS/phase,
// conflict-free (eighth e at float offset e*36 -> bank group 4e).
// ---------------------------------------------------------------------------

#define B_   256
#define T_   1024
#define D_   256
#define U_   128
#define G_   384
#define SIG_ 20
#define M_   (B_ * T_)

typedef unsigned long long ull;

__device__ float g_xproj[(size_t)M_ * G_];
__device__ __nv_bfloat16 g_acat[(size_t)M_ * 512];
__device__ __nv_bfloat16 g_btcat[(size_t)G_ * 768];
__device__ float g_gbias[G_];

__device__ __forceinline__ ull pack2f(float lo, float hi) {
    ull r; asm("mov.b64 %0, {%1,%2};" : "=l"(r) : "f"(lo), "f"(hi)); return r;
}
__device__ __forceinline__ void unpack2f(ull v, float& lo, float& hi) {
    asm("mov.b64 {%0,%1}, %2;" : "=f"(lo), "=f"(hi) : "l"(v));
}
__device__ __forceinline__ ull ffma2(ull a, ull b, ull c) {
    ull d; asm("fma.rn.f32x2 %0, %1, %2, %3;" : "=l"(d) : "l"(a), "l"(b), "l"(c)); return d;
}
__device__ __forceinline__ float fsig(float x) {
    return __fdividef(1.0f, 1.0f + __expf(-x));
}
__device__ __forceinline__ float ftanh(float x) {
    return 1.0f - 2.0f * __fdividef(1.0f, __expf(2.0f * x) + 1.0f);
}
__device__ __forceinline__ uint32_t smem_u32(const void* p) {
    uint32_t a;
    asm("{ .reg .u64 t; cvta.to.shared.u64 t, %1; cvt.u32.u64 %0, t; }" : "=r"(a) : "l"(p));
    return a;
}
__device__ __forceinline__ void ldsm4(uint32_t* r, uint32_t addr) {
    asm volatile("ldmatrix.sync.aligned.m8n8.x4.shared.b16 {%0,%1,%2,%3}, [%4];"
        : "=r"(r[0]), "=r"(r[1]), "=r"(r[2]), "=r"(r[3]) : "r"(addr));
}
__device__ __forceinline__ void mma16816(float* d, const uint32_t* a, const uint32_t* b) {
    asm volatile(
        "mma.sync.aligned.m16n8k16.row.col.f32.bf16.bf16.f32 "
        "{%0,%1,%2,%3}, {%4,%5,%6,%7}, {%8,%9}, {%0,%1,%2,%3};"
        : "+f"(d[0]), "+f"(d[1]), "+f"(d[2]), "+f"(d[3])
        : "r"(a[0]), "r"(a[1]), "r"(a[2]), "r"(a[3]), "r"(b[0]), "r"(b[1]));
}
__device__ __forceinline__ void cpasync16(uint32_t dst, const void* src) {
    asm volatile("cp.async.cg.shared.global [%0], [%1], 16;" :: "r"(dst), "l"(src) : "memory");
}
#define CP_COMMIT() asm volatile("cp.async.commit_group;" ::: "memory")
#define CP_WAITG(n) asm volatile("cp.async.wait_group %0;" :: "n"(n) : "memory")

// ===========================================================================
__global__ __launch_bounds__(256)
void conv_a(const float* __restrict__ in) {
    size_t v = (size_t)blockIdx.x * 256 + threadIdx.x;
    size_t m = v >> 6;
    int c4 = (int)(v & 63);
    float4 a = ((const float4*)in)[v];
    __nv_bfloat16 h0 = __float2bfloat16(a.x), h1 = __float2bfloat16(a.y);
    __nv_bfloat16 h2 = __float2bfloat16(a.z), h3 = __float2bfloat16(a.w);
    __nv_bfloat16 l0 = __float2bfloat16(a.x - __bfloat162float(h0));
    __nv_bfloat16 l1 = __float2bfloat16(a.y - __bfloat162float(h1));
    __nv_bfloat16 l2 = __float2bfloat16(a.z - __bfloat162float(h2));
    __nv_bfloat16 l3 = __float2bfloat16(a.w - __bfloat162float(h3));
    __nv_bfloat162* dst = (__nv_bfloat162*)(g_acat + m * 512 + c4 * 4);
    dst[0] = __nv_bfloat162(h0, h1);
    dst[1] = __nv_bfloat162(h2, h3);
    __nv_bfloat162* dstl = (__nv_bfloat162*)(g_acat + m * 512 + 256 + c4 * 4);
    dstl[0] = __nv_bfloat162(l0, l1);
    dstl[1] = __nv_bfloat162(l2, l3);
}

// ===========================================================================
__global__ __launch_bounds__(384)
void conv_b(const float* __restrict__ ik, const float* __restrict__ bias) {
    int k = blockIdx.x;
    int n = threadIdx.x;
    float b = ik[(size_t)k * G_ + n];
    __nv_bfloat16 bh = __float2bfloat16(b);
    __nv_bfloat16 bl = __float2bfloat16(b - __bfloat162float(bh));
    __nv_bfloat16* row = g_btcat + (size_t)n * 768;
    row[k] = bh;
    row[256 + k] = bh;
    row[512 + k] = bl;
    if (k == 0) {
        float gb;
        if (n < U_)          gb = bias[n];
        else if (n < 2 * U_) gb = bias[2 * U_ + (n - U_)];
        else                 gb = bias[3 * U_ + (n - 2 * U_)];
        g_gbias[n] = gb;
    }
}

// ===========================================================================
// K1: x_proj GEMM (round-7 pipeline) + gate bias in epilogue.
// ===========================================================================
#define ABUF(s) ((s) * 16384)
#define BBUF(s) (49152 + (s) * 16384)

__global__ __launch_bounds__(256, 2)
void xproj_mma(void) {
    extern __shared__ __align__(1024) char dsm[];
    const uint32_t sb = smem_u32(dsm);

    const int tid = threadIdx.x;
    const int wid = tid >> 5;
    const int lane = tid & 31;
    const int wm = wid & 3;
    const int wn = wid >> 2;
    const int n0 = blockIdx.x * 128;
    const size_t m0 = (size_t)blockIdx.y * 128;

    const int lrow = tid >> 3;
    const int c16  = tid & 7;
    uint32_t cpOff[4];
#pragma unroll
    for (int i = 0; i < 4; i++) {
        int row = lrow + 32 * i;
        cpOff[i] = (uint32_t)(row * 128 + ((c16 * 16) ^ ((row & 7) << 4)));
    }
    const __nv_bfloat16* aSrc[4];
    const __nv_bfloat16* bSrc[4];
#pragma unroll
    for (int i = 0; i < 4; i++) {
        int row = lrow + 32 * i;
        aSrc[i] = g_acat + (m0 + row) * 512 + c16 * 8;
        bSrc[i] = g_btcat + (size_t)(n0 + row) * 768 + c16 * 8;
    }

    const int a_row0 = wm * 32 + (lane & 15);
    const int a_hi   = lane >> 4;
    const uint32_t a_xor = (uint32_t)((a_row0 & 7) << 4);
    const uint32_t aOff0 = (uint32_t)(a_row0 * 128);
    const uint32_t aOff1 = (uint32_t)((a_row0 + 16) * 128);

    const int b_row_l = wn * 64 + (lane & 7) + ((lane >> 4) << 3);
    const int b_hi    = (lane >> 3) & 1;
    const uint32_t b_xor = (uint32_t)((b_row_l & 7) << 4);
    uint32_t bOff[4];
#pragma unroll
    for (int p = 0; p < 4; p++)
        bOff[p] = (uint32_t)((b_row_l + p * 16) * 128);

    float d[2][8][4];
#pragma unroll
    for (int af = 0; af < 2; af++)
#pragma unroll
        for (int p = 0; p < 8; p++)
#pragma unroll
            for (int q = 0; q < 4; q++) d[af][p][q] = 0.0f;

#pragma unroll
    for (int pc = 0; pc < 2; pc++) {
#pragma unroll
        for (int i = 0; i < 4; i++) cpasync16(sb + ABUF(pc) + cpOff[i], aSrc[i] + pc * 64);
#pragma unroll
        for (int i = 0; i < 4; i++) cpasync16(sb + BBUF(pc) + cpOff[i], bSrc[i] + pc * 64);
        CP_COMMIT();
    }

#pragma unroll
    for (int c = 0; c < 12; c++) {
        const int buf = c % 3;

        if (c < 11) { CP_WAITG(1); } else { CP_WAITG(0); }
        __syncthreads();

        if (c + 2 < 12) {
            const int cn = c + 2;
            const int nbuf = cn % 3;
            const int akc = (cn < 8) ? cn * 64 : (cn - 8) * 64;
            const int bkc = cn * 64;
#pragma unroll
            for (int i = 0; i < 4; i++) cpasync16(sb + ABUF(nbuf) + cpOff[i], aSrc[i] + akc);
#pragma unroll
            for (int i = 0; i < 4; i++) cpasync16(sb + BBUF(nbuf) + cpOff[i], bSrc[i] + bkc);
            CP_COMMIT();
        }

        const uint32_t aB0 = sb + ABUF(buf) + aOff0;
        const uint32_t aB1 = sb + ABUF(buf) + aOff1;
        const uint32_t bBs = sb + BBUF(buf);
#pragma unroll
        for (int ks = 0; ks < 4; ks++) {
            uint32_t af0[4], af1[4];
            uint32_t koffA = (uint32_t)(((ks * 2 + a_hi) * 16) ^ a_xor);
            ldsm4(af0, aB0 + koffA);
            ldsm4(af1, aB1 + koffA);
            uint32_t koffB = (uint32_t)(((ks * 2 + b_hi) * 16) ^ b_xor);
#pragma unroll
            for (int p = 0; p < 4; p++) {
                uint32_t bf[4];
                ldsm4(bf, bBs + bOff[p] + koffB);
                mma16816(d[0][p * 2],     af0, &bf[0]);
                mma16816(d[0][p * 2 + 1], af0, &bf[2]);
                mma16816(d[1][p * 2],     af1, &bf[0]);
                mma16816(d[1][p * 2 + 1], af1, &bf[2]);
            }
        }
    }

    const int colb = n0 + wn * 64 + 2 * (lane & 3);
#pragma unroll
    for (int af = 0; af < 2; af++) {
        const int mrow = (int)m0 + wm * 32 + af * 16 + (lane >> 2);
#pragma unroll
        for (int p = 0; p < 8; p++) {
            int col = colb + p * 8;
            float2 gb = *(const float2*)(g_gbias + col);
            *(float2*)(g_xproj + (size_t)mrow * G_ + col) =
                make_float2(d[af][p][0] + gb.x, d[af][p][1] + gb.y);
            *(float2*)(g_xproj + (size_t)(mrow + 8) * G_ + col) =
                make_float2(d[af][p][2] + gb.x, d[af][p][3] + gb.y);
        }
    }
}

// ===========================================================================
// K2: row-staggered scan, 8-way k-split, column-pair packed W, DUPLICATED h.
// h stored as (h,h) float2 at eighth (u>>4)*36 + 2*(u&15); readers LDS.128
// two packed k-values per load (8 loads/phase, 1 wavefront each).
// ===========================================================================
#define HIDX2(u) (((u) >> 4) * 36 + 2 * ((u) & 15))

__global__ __launch_bounds__(384, 1)
void efm_scan(const float* __restrict__ sigs,
              const float* __restrict__ rk,
              const float* __restrict__ fk,
              const float* __restrict__ bias,
              float* __restrict__ out)
{
    const int j = threadIdx.x;
    const int r0 = blockIdx.x * 2;

    __shared__ __align__(16) float sh[2][288];       // 8 eighths x 36 floats
    __shared__ __align__(16) float sg[2][G_];
    __shared__ __align__(16) float sF[SIG_][U_];
    __shared__ float ssig[2][2][SIG_];
    __shared__ float sfv[2][2][U_];

    // --- W eighth kq for column pairs (j^2c, j^2c+1), c=0..3 ---
    const int kq = j & 7;
    const int kb = kq * 16;
    ull W2[4][16];
#pragma unroll
    for (int c = 0; c < 4; c++) {
        int cl = j ^ (2 * c);
        int ch = j ^ (2 * c + 1);
#pragma unroll
        for (int q = 0; q < 16; q++) {
            int k = kb + q;
            W2[c][q] = pack2f(rk[(size_t)k * G_ + cl], rk[(size_t)k * G_ + ch]);
        }
    }

    for (int idx = j; idx < SIG_ * U_; idx += 384)
        (&sF[0][0])[idx] = fk[idx];

    if (j < U_) {
        *(float2*)&sh[0][HIDX2(j)] = make_float2(0.0f, 0.0f);
        *(float2*)&sh[1][HIDX2(j)] = make_float2(0.0f, 0.0f);
    }

    const bool actSig = (j < U_) || (j >= 2 * U_);
    const bool isU0 = (j < U_);
    const bool isU1 = (j >= U_) && (j < 2 * U_);
    const int u = j & (U_ - 1);
    float creg = 0.0f;
    float* op = out + ((size_t)(r0 + (isU1 ? 1 : 0)) * T_) * U_ + u;

    const bool isF = (j >= 2 * U_);
    const int fu = isF ? (j - 2 * U_) : 0;
    const float fbias = bias[U_ + fu];

    const bool isL = (j >= 296) && (j < 296 + 2 * SIG_);
    const int lrw = isL ? (j - 296) / SIG_ : 0;
    const int ls  = isL ? (j - 296) % SIG_ : 0;
    const float* sigp = sigs + ((size_t)(r0 + lrw) * T_) * SIG_ + ls;

    const float* xp0 = g_xproj + ((size_t)r0 * T_) * G_ + j;
    const float* xp1 = g_xproj + ((size_t)(r0 + 1) * T_) * G_ + j;

    // h base for this thread's eighth (float offset kq*36, 16B aligned)
    const float* hb0 = &sh[0][kq * 36];
    const float* hb1 = &sh[1][kq * 36];

    // ---- prologue ----
    if (isL) ssig[0][lrw][ls] = sigp[0];
    float sreg = isL ? sigp[SIG_] : 0.0f;
    float xr00 = xp0[0];
    float x1 = xp1[0];
    float x0 = xp0[G_];
    __syncthreads();

    sg[0][j] = actSig ? fsig(xr00) : ftanh(xr00);
    if (isF) {
        float a0 = fbias, a1 = fbias;
#pragma unroll
        for (int s = 0; s < SIG_; s++) {
            float cf = sF[s][fu];
            a0 += ssig[0][0][s] * cf;
            a1 += ssig[0][1][s] * cf;
        }
        sfv[0][0][fu] = fsig(a0);
        sfv[0][1][fu] = fsig(a1);
    }
    __syncthreads();

    for (int t = 0; t < T_; t++) {
        const int pb = (t + 1) & 1;

        // ================= Phase A(t) =================
        if (isL) {
            ssig[pb][lrw][ls] = sreg;
            int t2 = (t + 2 < T_) ? t + 2 : T_ - 1;
            sreg = sigp[(size_t)t2 * SIG_];
        }
        int tn1 = (t + 1 < T_) ? t + 1 : T_ - 1;
        float nx1 = xp1[(size_t)tn1 * G_];

        {   // GEMV r1(t): 8 packed LDS.128, 4 col-pair chains
            ull ac[4] = {0ULL, 0ULL, 0ULL, 0ULL};
#pragma unroll
            for (int i = 0; i < 8; i++) {
                ulonglong2 hv = *(const ulonglong2*)(hb1 + 4 * i);
#pragma unroll
                for (int c = 0; c < 4; c++) {
                    ac[c] = ffma2(hv.x, W2[c][2 * i],     ac[c]);
                    ac[c] = ffma2(hv.y, W2[c][2 * i + 1], ac[c]);
                }
            }
            float p[8];
#pragma unroll
            for (int c = 0; c < 4; c++) unpack2f(ac[c], p[2 * c], p[2 * c + 1]);
            float q0 = p[0] + __shfl_xor_sync(0xFFFFFFFFu, p[1], 1);
            float q2 = p[2] + __shfl_xor_sync(0xFFFFFFFFu, p[3], 1);
            float q4 = p[4] + __shfl_xor_sync(0xFFFFFFFFu, p[5], 1);
            float q6 = p[6] + __shfl_xor_sync(0xFFFFFFFFu, p[7], 1);
            float r0s = q0 + __shfl_xor_sync(0xFFFFFFFFu, q2, 2);
            float r4s = q4 + __shfl_xor_sync(0xFFFFFFFFu, q6, 2);
            float g = r0s + __shfl_xor_sync(0xFFFFFFFFu, r4s, 4) + x1;
            sg[1][j] = actSig ? fsig(g) : ftanh(g);
        }
        if (isU0) {   // update r0(t)
            float fcur = sfv[t & 1][0][u];
            float ig = sg[0][u];
            float ch = sg[0][U_ + u];
            float og = sg[0][2 * U_ + u];
            creg = fcur * creg + ig * ch;
            float hn = og * ftanh(creg);
            *(float2*)&sh[0][HIDX2(u)] = make_float2(hn, hn);
            op[(size_t)t * U_] = hn;
        }
        __syncthreads();

        // ================= Phase B(t) =================
        int tn2 = (t + 2 < T_) ? t + 2 : T_ - 1;
        float nx0 = xp0[(size_t)tn2 * G_];

        if (t + 1 < T_) {   // GEMV r0(t+1)
            ull ac[4] = {0ULL, 0ULL, 0ULL, 0ULL};
#pragma unroll
            for (int i = 0; i < 8; i++) {
                ulonglong2 hv = *(const ulonglong2*)(hb0 + 4 * i);
#pragma unroll
                for (int c = 0; c < 4; c++) {
                    ac[c] = ffma2(hv.x, W2[c][2 * i],     ac[c]);
                    ac[c] = ffma2(hv.y, W2[c][2 * i + 1], ac[c]);
                }
            }
            float p[8];
#pragma unroll
            for (int c = 0; c < 4; c++) unpack2f(ac[c], p[2 * c], p[2 * c + 1]);
            float q0 = p[0] + __shfl_xor_sync(0xFFFFFFFFu, p[1], 1);
            float q2 = p[2] + __shfl_xor_sync(0xFFFFFFFFu, p[3], 1);
            float q4 = p[4] + __shfl_xor_sync(0xFFFFFFFFu, p[5], 1);
            float q6 = p[6] + __shfl_xor_sync(0xFFFFFFFFu, p[7], 1);
            float r0s = q0 + __shfl_xor_sync(0xFFFFFFFFu, q2, 2);
            float r4s = q4 + __shfl_xor_sync(0xFFFFFFFFu, q6, 2);
            float g = r0s + __shfl_xor_sync(0xFFFFFFFFu, r4s, 4) + x0;
            sg[0][j] = actSig ? fsig(g) : ftanh(g);
        }
        if (isU1) {   // update r1(t)
            float fcur = sfv[t & 1][1][u];
            float ig = sg[1][u];
            float ch = sg[1][U_ + u];
            float og = sg[1][2 * U_ + u];
            creg = fcur * creg + ig * ch;
            float hn = og * ftanh(creg);
            *(float2*)&sh[1][HIDX2(u)] = make_float2(hn, hn);
            op[(size_t)t * U_] = hn;
        }
        if (isF) {   // f(t+1) both rows
            float a0 = fbias, a1 = fbias;
#pragma unroll
            for (int s = 0; s < SIG_; s++) {
                float cf = sF[s][fu];
                a0 += ssig[pb][0][s] * cf;
                a1 += ssig[pb][1][s] * cf;
            }
            sfv[pb][0][fu] = fsig(a0);
            sfv[pb][1][fu] = fsig(a1);
        }
        __syncthreads();

        x1 = nx1;
        x0 = nx0;
    }
}

// ===========================================================================
extern "C" void kernel_launch(void* const* d_in, const int* in_sizes, int n_in,
                              void* d_out, int out_size) {
    const float* inputs = (const float*)d_in[0];
    const float* sigs   = (const float*)d_in[1];
    const float* ik     = (const float*)d_in[2];
    const float* rk     = (const float*)d_in[3];
    const float* fk     = (const float*)d_in[4];
    const float* bias   = (const float*)d_in[5];
    float* out = (float*)d_out;

    cudaFuncSetAttribute(xproj_mma, cudaFuncAttributeMaxDynamicSharedMemorySize, 98304);

    conv_a<<<(M_ * 64) / 256, 256>>>(inputs);
    conv_b<<<D_, 384>>>(ik, bias);

    dim3 gg(G_ / 128, M_ / 128);   // (3, 2048)
    xproj_mma<<<gg, 256, 98304>>>();

    efm_scan<<<B_ / 2, 384>>>(sigs, rk, fk, bias, out);
}

// round 17
// speedup vs baseline: 1.0354x; 1.0354x over previous
#include <cuda_runtime.h>
#include <cuda_bf16.h>
#include <cstdint>

// ---------------------------------------------------------------------------
// EfmLSTM FINAL (= round 15, best verified 1487us):
//   conv_a: inputs -> A_cat bf16 [ah|al]; conv_b: ik -> Bt_cat [bh|bh|bl]+bias
//   xproj_mma: mma.sync bf16 split-K GEMM, 3-stage cp.async, bias epilogue
//   efm_scan: row-staggered, 8-way lane k-split GEMV, col-pair packed W,
//             fused forget gate; 128 CTAs x 384 thr, W in registers.
// ---------------------------------------------------------------------------

#define B_   256
#define T_   1024
#define D_   256
#define U_   128
#define G_   384
#define SIG_ 20
#define M_   (B_ * T_)

typedef unsigned long long ull;

__device__ float g_xproj[(size_t)M_ * G_];
__device__ __nv_bfloat16 g_acat[(size_t)M_ * 512];
__device__ __nv_bfloat16 g_btcat[(size_t)G_ * 768];
__device__ float g_gbias[G_];

__device__ __forceinline__ ull pack2f(float lo, float hi) {
    ull r; asm("mov.b64 %0, {%1,%2};" : "=l"(r) : "f"(lo), "f"(hi)); return r;
}
__device__ __forceinline__ void unpack2f(ull v, float& lo, float& hi) {
    asm("mov.b64 {%0,%1}, %2;" : "=f"(lo), "=f"(hi) : "l"(v));
}
__device__ __forceinline__ ull ffma2(ull a, ull b, ull c) {
    ull d; asm("fma.rn.f32x2 %0, %1, %2, %3;" : "=l"(d) : "l"(a), "l"(b), "l"(c)); return d;
}
__device__ __forceinline__ float fsig(float x) {
    return __fdividef(1.0f, 1.0f + __expf(-x));
}
__device__ __forceinline__ float ftanh(float x) {
    return 1.0f - 2.0f * __fdividef(1.0f, __expf(2.0f * x) + 1.0f);
}
__device__ __forceinline__ uint32_t smem_u32(const void* p) {
    uint32_t a;
    asm("{ .reg .u64 t; cvta.to.shared.u64 t, %1; cvt.u32.u64 %0, t; }" : "=r"(a) : "l"(p));
    return a;
}
__device__ __forceinline__ void ldsm4(uint32_t* r, uint32_t addr) {
    asm volatile("ldmatrix.sync.aligned.m8n8.x4.shared.b16 {%0,%1,%2,%3}, [%4];"
        : "=r"(r[0]), "=r"(r[1]), "=r"(r[2]), "=r"(r[3]) : "r"(addr));
}
__device__ __forceinline__ void mma16816(float* d, const uint32_t* a, const uint32_t* b) {
    asm volatile(
        "mma.sync.aligned.m16n8k16.row.col.f32.bf16.bf16.f32 "
        "{%0,%1,%2,%3}, {%4,%5,%6,%7}, {%8,%9}, {%0,%1,%2,%3};"
        : "+f"(d[0]), "+f"(d[1]), "+f"(d[2]), "+f"(d[3])
        : "r"(a[0]), "r"(a[1]), "r"(a[2]), "r"(a[3]), "r"(b[0]), "r"(b[1]));
}
__device__ __forceinline__ void cpasync16(uint32_t dst, const void* src) {
    asm volatile("cp.async.cg.shared.global [%0], [%1], 16;" :: "r"(dst), "l"(src) : "memory");
}
#define CP_COMMIT() asm volatile("cp.async.commit_group;" ::: "memory")
#define CP_WAITG(n) asm volatile("cp.async.wait_group %0;" :: "n"(n) : "memory")

// ===========================================================================
__global__ __launch_bounds__(256)
void conv_a(const float* __restrict__ in) {
    size_t v = (size_t)blockIdx.x * 256 + threadIdx.x;
    size_t m = v >> 6;
    int c4 = (int)(v & 63);
    float4 a = ((const float4*)in)[v];
    __nv_bfloat16 h0 = __float2bfloat16(a.x), h1 = __float2bfloat16(a.y);
    __nv_bfloat16 h2 = __float2bfloat16(a.z), h3 = __float2bfloat16(a.w);
    __nv_bfloat16 l0 = __float2bfloat16(a.x - __bfloat162float(h0));
    __nv_bfloat16 l1 = __float2bfloat16(a.y - __bfloat162float(h1));
    __nv_bfloat16 l2 = __float2bfloat16(a.z - __bfloat162float(h2));
    __nv_bfloat16 l3 = __float2bfloat16(a.w - __bfloat162float(h3));
    __nv_bfloat162* dst = (__nv_bfloat162*)(g_acat + m * 512 + c4 * 4);
    dst[0] = __nv_bfloat162(h0, h1);
    dst[1] = __nv_bfloat162(h2, h3);
    __nv_bfloat162* dstl = (__nv_bfloat162*)(g_acat + m * 512 + 256 + c4 * 4);
    dstl[0] = __nv_bfloat162(l0, l1);
    dstl[1] = __nv_bfloat162(l2, l3);
}

// ===========================================================================
__global__ __launch_bounds__(384)
void conv_b(const float* __restrict__ ik, const float* __restrict__ bias) {
    int k = blockIdx.x;
    int n = threadIdx.x;
    float b = ik[(size_t)k * G_ + n];
    __nv_bfloat16 bh = __float2bfloat16(b);
    __nv_bfloat16 bl = __float2bfloat16(b - __bfloat162float(bh));
    __nv_bfloat16* row = g_btcat + (size_t)n * 768;
    row[k] = bh;
    row[256 + k] = bh;
    row[512 + k] = bl;
    if (k == 0) {
        float gb;
        if (n < U_)          gb = bias[n];
        else if (n < 2 * U_) gb = bias[2 * U_ + (n - U_)];
        else                 gb = bias[3 * U_ + (n - 2 * U_)];
        g_gbias[n] = gb;
    }
}

// ===========================================================================
// K1: x_proj GEMM (3-stage cp.async pipeline) + gate bias in epilogue.
// ===========================================================================
#define ABUF(s) ((s) * 16384)
#define BBUF(s) (49152 + (s) * 16384)

__global__ __launch_bounds__(256, 2)
void xproj_mma(void) {
    extern __shared__ __align__(1024) char dsm[];
    const uint32_t sb = smem_u32(dsm);

    const int tid = threadIdx.x;
    const int wid = tid >> 5;
    const int lane = tid & 31;
    const int wm = wid & 3;
    const int wn = wid >> 2;
    const int n0 = blockIdx.x * 128;
    const size_t m0 = (size_t)blockIdx.y * 128;

    const int lrow = tid >> 3;
    const int c16  = tid & 7;
    uint32_t cpOff[4];
#pragma unroll
    for (int i = 0; i < 4; i++) {
        int row = lrow + 32 * i;
        cpOff[i] = (uint32_t)(row * 128 + ((c16 * 16) ^ ((row & 7) << 4)));
    }
    const __nv_bfloat16* aSrc[4];
    const __nv_bfloat16* bSrc[4];
#pragma unroll
    for (int i = 0; i < 4; i++) {
        int row = lrow + 32 * i;
        aSrc[i] = g_acat + (m0 + row) * 512 + c16 * 8;
        bSrc[i] = g_btcat + (size_t)(n0 + row) * 768 + c16 * 8;
    }

    const int a_row0 = wm * 32 + (lane & 15);
    const int a_hi   = lane >> 4;
    const uint32_t a_xor = (uint32_t)((a_row0 & 7) << 4);
    const uint32_t aOff0 = (uint32_t)(a_row0 * 128);
    const uint32_t aOff1 = (uint32_t)((a_row0 + 16) * 128);

    const int b_row_l = wn * 64 + (lane & 7) + ((lane >> 4) << 3);
    const int b_hi    = (lane >> 3) & 1;
    const uint32_t b_xor = (uint32_t)((b_row_l & 7) << 4);
    uint32_t bOff[4];
#pragma unroll
    for (int p = 0; p < 4; p++)
        bOff[p] = (uint32_t)((b_row_l + p * 16) * 128);

    float d[2][8][4];
#pragma unroll
    for (int af = 0; af < 2; af++)
#pragma unroll
        for (int p = 0; p < 8; p++)
#pragma unroll
            for (int q = 0; q < 4; q++) d[af][p][q] = 0.0f;

#pragma unroll
    for (int pc = 0; pc < 2; pc++) {
#pragma unroll
        for (int i = 0; i < 4; i++) cpasync16(sb + ABUF(pc) + cpOff[i], aSrc[i] + pc * 64);
#pragma unroll
        for (int i = 0; i < 4; i++) cpasync16(sb + BBUF(pc) + cpOff[i], bSrc[i] + pc * 64);
        CP_COMMIT();
    }

#pragma unroll
    for (int c = 0; c < 12; c++) {
        const int buf = c % 3;

        if (c < 11) { CP_WAITG(1); } else { CP_WAITG(0); }
        __syncthreads();

        if (c + 2 < 12) {
            const int cn = c + 2;
            const int nbuf = cn % 3;
            const int akc = (cn < 8) ? cn * 64 : (cn - 8) * 64;
            const int bkc = cn * 64;
#pragma unroll
            for (int i = 0; i < 4; i++) cpasync16(sb + ABUF(nbuf) + cpOff[i], aSrc[i] + akc);
#pragma unroll
            for (int i = 0; i < 4; i++) cpasync16(sb + BBUF(nbuf) + cpOff[i], bSrc[i] + bkc);
            CP_COMMIT();
        }

        const uint32_t aB0 = sb + ABUF(buf) + aOff0;
        const uint32_t aB1 = sb + ABUF(buf) + aOff1;
        const uint32_t bBs = sb + BBUF(buf);
#pragma unroll
        for (int ks = 0; ks < 4; ks++) {
            uint32_t af0[4], af1[4];
            uint32_t koffA = (uint32_t)(((ks * 2 + a_hi) * 16) ^ a_xor);
            ldsm4(af0, aB0 + koffA);
            ldsm4(af1, aB1 + koffA);
            uint32_t koffB = (uint32_t)(((ks * 2 + b_hi) * 16) ^ b_xor);
#pragma unroll
            for (int p = 0; p < 4; p++) {
                uint32_t bf[4];
                ldsm4(bf, bBs + bOff[p] + koffB);
                mma16816(d[0][p * 2],     af0, &bf[0]);
                mma16816(d[0][p * 2 + 1], af0, &bf[2]);
                mma16816(d[1][p * 2],     af1, &bf[0]);
                mma16816(d[1][p * 2 + 1], af1, &bf[2]);
            }
        }
    }

    const int colb = n0 + wn * 64 + 2 * (lane & 3);
#pragma unroll
    for (int af = 0; af < 2; af++) {
        const int mrow = (int)m0 + wm * 32 + af * 16 + (lane >> 2);
#pragma unroll
        for (int p = 0; p < 8; p++) {
            int col = colb + p * 8;
            float2 gb = *(const float2*)(g_gbias + col);
            *(float2*)(g_xproj + (size_t)mrow * G_ + col) =
                make_float2(d[af][p][0] + gb.x, d[af][p][1] + gb.y);
            *(float2*)(g_xproj + (size_t)(mrow + 8) * G_ + col) =
                make_float2(d[af][p][2] + gb.x, d[af][p][3] + gb.y);
        }
    }
}

// ===========================================================================
// K2: row-staggered scan, 8-way k-split, column-pair packed W.
// h layout: 8 eighths of 16 floats, each padded +4 -> eighth e at e*20.
// Thread j: kq=j&7 of K for columns j^0..j^7 (4 packed col-pair chains).
// Per phase: 4 LDS.128 (8 disjoint-bank lines/instr) + 64 FFMA2 + 7 shfl.
// ===========================================================================
#define HIDX(k) ((k) + 4 * ((k) >> 4))

__global__ __launch_bounds__(384, 1)
void efm_scan(const float* __restrict__ sigs,
              const float* __restrict__ rk,
              const float* __restrict__ fk,
              const float* __restrict__ bias,
              float* __restrict__ out)
{
    const int j = threadIdx.x;
    const int r0 = blockIdx.x * 2;

    __shared__ __align__(16) float sh[2][160];       // 8 padded eighths
    __shared__ __align__(16) float sg[2][G_];
    __shared__ __align__(16) float sF[SIG_][U_];
    __shared__ float ssig[2][2][SIG_];
    __shared__ float sfv[2][2][U_];

    // --- W eighth kq for column pairs (j^2c, j^2c+1), c=0..3 ---
    const int kq = j & 7;
    const int kb = kq * 16;
    ull W2[4][16];
#pragma unroll
    for (int c = 0; c < 4; c++) {
        int cl = j ^ (2 * c);
        int ch = j ^ (2 * c + 1);
#pragma unroll
        for (int q = 0; q < 16; q++) {
            int k = kb + q;
            W2[c][q] = pack2f(rk[(size_t)k * G_ + cl], rk[(size_t)k * G_ + ch]);
        }
    }

    for (int idx = j; idx < SIG_ * U_; idx += 384)
        (&sF[0][0])[idx] = fk[idx];

    if (j < U_) {
        sh[0][HIDX(j)] = 0.0f;
        sh[1][HIDX(j)] = 0.0f;
    }

    const bool actSig = (j < U_) || (j >= 2 * U_);
    const bool isU0 = (j < U_);
    const bool isU1 = (j >= U_) && (j < 2 * U_);
    const int u = j & (U_ - 1);
    float creg = 0.0f;
    float* op = out + ((size_t)(r0 + (isU1 ? 1 : 0)) * T_) * U_ + u;

    const bool isF = (j >= 2 * U_);
    const int fu = isF ? (j - 2 * U_) : 0;
    const float fbias = bias[U_ + fu];

    const bool isL = (j >= 296) && (j < 296 + 2 * SIG_);
    const int lrw = isL ? (j - 296) / SIG_ : 0;
    const int ls  = isL ? (j - 296) % SIG_ : 0;
    const float* sigp = sigs + ((size_t)(r0 + lrw) * T_) * SIG_ + ls;

    const float* xp0 = g_xproj + ((size_t)r0 * T_) * G_ + j;
    const float* xp1 = g_xproj + ((size_t)(r0 + 1) * T_) * G_ + j;

    // h base for this thread's eighth (float offset kq*20, 16B aligned)
    const float* hb0 = &sh[0][kq * 20];
    const float* hb1 = &sh[1][kq * 20];

    // ---- prologue ----
    if (isL) ssig[0][lrw][ls] = sigp[0];
    float sreg = isL ? sigp[SIG_] : 0.0f;
    float xr00 = xp0[0];
    float x1 = xp1[0];
    float x0 = xp0[G_];
    __syncthreads();

    sg[0][j] = actSig ? fsig(xr00) : ftanh(xr00);
    if (isF) {
        float a0 = fbias, a1 = fbias;
#pragma unroll
        for (int s = 0; s < SIG_; s++) {
            float cf = sF[s][fu];
            a0 += ssig[0][0][s] * cf;
            a1 += ssig[0][1][s] * cf;
        }
        sfv[0][0][fu] = fsig(a0);
        sfv[0][1][fu] = fsig(a1);
    }
    __syncthreads();

    for (int t = 0; t < T_; t++) {
        const int pb = (t + 1) & 1;

        // ================= Phase A(t) =================
        if (isL) {
            ssig[pb][lrw][ls] = sreg;
            int t2 = (t + 2 < T_) ? t + 2 : T_ - 1;
            sreg = sigp[(size_t)t2 * SIG_];
        }
        int tn1 = (t + 1 < T_) ? t + 1 : T_ - 1;
        float nx1 = xp1[(size_t)tn1 * G_];

        {   // GEMV r1(t), 8-way k-split, col-pair chains
            ull ac[4] = {0ULL, 0ULL, 0ULL, 0ULL};
#pragma unroll
            for (int i = 0; i < 4; i++) {
                float4 hv = *(const float4*)(hb1 + 4 * i);
                ull hp0 = pack2f(hv.x, hv.x);
                ull hp1 = pack2f(hv.y, hv.y);
                ull hp2 = pack2f(hv.z, hv.z);
                ull hp3 = pack2f(hv.w, hv.w);
#pragma unroll
                for (int c = 0; c < 4; c++) {
                    ac[c] = ffma2(hp0, W2[c][4 * i + 0], ac[c]);
                    ac[c] = ffma2(hp1, W2[c][4 * i + 1], ac[c]);
                    ac[c] = ffma2(hp2, W2[c][4 * i + 2], ac[c]);
                    ac[c] = ffma2(hp3, W2[c][4 * i + 3], ac[c]);
                }
            }
            float p[8];
#pragma unroll
            for (int c = 0; c < 4; c++) unpack2f(ac[c], p[2 * c], p[2 * c + 1]);
            float q0 = p[0] + __shfl_xor_sync(0xFFFFFFFFu, p[1], 1);
            float q2 = p[2] + __shfl_xor_sync(0xFFFFFFFFu, p[3], 1);
            float q4 = p[4] + __shfl_xor_sync(0xFFFFFFFFu, p[5], 1);
            float q6 = p[6] + __shfl_xor_sync(0xFFFFFFFFu, p[7], 1);
            float r0s = q0 + __shfl_xor_sync(0xFFFFFFFFu, q2, 2);
            float r4s = q4 + __shfl_xor_sync(0xFFFFFFFFu, q6, 2);
            float g = r0s + __shfl_xor_sync(0xFFFFFFFFu, r4s, 4) + x1;
            sg[1][j] = actSig ? fsig(g) : ftanh(g);
        }
        if (isU0) {   // update r0(t)
            float fcur = sfv[t & 1][0][u];
            float ig = sg[0][u];
            float ch = sg[0][U_ + u];
            float og = sg[0][2 * U_ + u];
            creg = fcur * creg + ig * ch;
            float hn = og * ftanh(creg);
            sh[0][HIDX(u)] = hn;
            op[(size_t)t * U_] = hn;
        }
        __syncthreads();

        // ================= Phase B(t) =================
        int tn2 = (t + 2 < T_) ? t + 2 : T_ - 1;
        float nx0 = xp0[(size_t)tn2 * G_];

        if (t + 1 < T_) {   // GEMV r0(t+1)
            ull ac[4] = {0ULL, 0ULL, 0ULL, 0ULL};
#pragma unroll
            for (int i = 0; i < 4; i++) {
                float4 hv = *(const float4*)(hb0 + 4 * i);
                ull hp0 = pack2f(hv.x, hv.x);
                ull hp1 = pack2f(hv.y, hv.y);
                ull hp2 = pack2f(hv.z, hv.z);
                ull hp3 = pack2f(hv.w, hv.w);
#pragma unroll
                for (int c = 0; c < 4; c++) {
                    ac[c] = ffma2(hp0, W2[c][4 * i + 0], ac[c]);
                    ac[c] = ffma2(hp1, W2[c][4 * i + 1], ac[c]);
                    ac[c] = ffma2(hp2, W2[c][4 * i + 2], ac[c]);
                    ac[c] = ffma2(hp3, W2[c][4 * i + 3], ac[c]);
                }
            }
            float p[8];
#pragma unroll
            for (int c = 0; c < 4; c++) unpack2f(ac[c], p[2 * c], p[2 * c + 1]);
            float q0 = p[0] + __shfl_xor_sync(0xFFFFFFFFu, p[1], 1);
            float q2 = p[2] + __shfl_xor_sync(0xFFFFFFFFu, p[3], 1);
            float q4 = p[4] + __shfl_xor_sync(0xFFFFFFFFu, p[5], 1);
            float q6 = p[6] + __shfl_xor_sync(0xFFFFFFFFu, p[7], 1);
            float r0s = q0 + __shfl_xor_sync(0xFFFFFFFFu, q2, 2);
            float r4s = q4 + __shfl_xor_sync(0xFFFFFFFFu, q6, 2);
            float g = r0s + __shfl_xor_sync(0xFFFFFFFFu, r4s, 4) + x0;
            sg[0][j] = actSig ? fsig(g) : ftanh(g);
        }
        if (isU1) {   // update r1(t)
            float fcur = sfv[t & 1][1][u];
            float ig = sg[1][u];
            float ch = sg[1][U_ + u];
            float og = sg[1][2 * U_ + u];
            creg = fcur * creg + ig * ch;
            float hn = og * ftanh(creg);
            sh[1][HIDX(u)] = hn;
            op[(size_t)t * U_] = hn;
        }
        if (isF) {   // f(t+1) both rows
            float a0 = fbias, a1 = fbias;
#pragma unroll
            for (int s = 0; s < SIG_; s++) {
                float cf = sF[s][fu];
                a0 += ssig[pb][0][s] * cf;
                a1 += ssig[pb][1][s] * cf;
            }
            sfv[pb][0][fu] = fsig(a0);
            sfv[pb][1][fu] = fsig(a1);
        }
        __syncthreads();

        x1 = nx1;
        x0 = nx0;
    }
}

// ===========================================================================
extern "C" void kernel_launch(void* const* d_in, const int* in_sizes, int n_in,
                              void* d_out, int out_size) {
    const float* inputs = (const float*)d_in[0];
    const float* sigs   = (const float*)d_in[1];
    const float* ik     = (const float*)d_in[2];
    const float* rk     = (const float*)d_in[3];
    const float* fk     = (const float*)d_in[4];
    const float* bias   = (const float*)d_in[5];
    float* out = (float*)d_out;

    cudaFuncSetAttribute(xproj_mma, cudaFuncAttributeMaxDynamicSharedMemorySize, 98304);

    conv_a<<<(M_ * 64) / 256, 256>>>(inputs);
    conv_b<<<D_, 384>>>(ik, bias);

    dim3 gg(G_ / 128, M_ / 128);   // (3, 2048)
    xproj_mma<<<gg, 256, 98304>>>();

    efm_scan<<<B_ / 2, 384>>>(sigs, rk, fk, bias, out);
}